// round 7
// baseline (speedup 1.0000x reference)
#include <cuda_runtime.h>
#include <math.h>

// Problem constants
#define Bc  4
#define Hc  16
#define Sc  2048
#define Dc  1024
#define DHc 64

// Scratch (device globals: allowed; no runtime allocation)
__device__ float g_q[(size_t)Bc * Hc * Sc * DHc];   // q * dh^-0.5, [b][h][s][d]
__device__ float g_k[(size_t)Bc * Hc * Sc * DHc];   // k,           [b][h][s][d]
__device__ float g_kmean[Bc * Hc * DHc];            // mean_s k,    [b][h][d]

// ---------------------------------------------------------------------------
// Kernel 1: fused q/k projection  C[m,n] = sum_k x[m,k]*W[n,k] + bias[n]
//   m = b*S + s  (M = 8192),  n = 2*(h*64+d)+c  (N = 2048), K = 1024
//   epilogue scatters c==0 -> g_q (scaled by 0.125), c==1 -> g_k
// ---------------------------------------------------------------------------
__global__ __launch_bounds__(256, 2)
void proj_kernel(const float* __restrict__ x, const float* __restrict__ W,
                 const float* __restrict__ bias) {
    __shared__ float As[16][132];
    __shared__ float Bs[16][132];

    const int m0  = blockIdx.y * 128;
    const int n0  = blockIdx.x * 128;
    const int tid = threadIdx.x;
    const int tm  = (tid >> 4) * 8;
    const int tn  = (tid & 15) * 8;

    float acc[8][8];
#pragma unroll
    for (int i = 0; i < 8; i++)
#pragma unroll
        for (int j = 0; j < 8; j++) acc[i][j] = 0.f;

    for (int k0 = 0; k0 < Dc; k0 += 16) {
        // load A tile (128 x 16) transposed -> As[k][m]
#pragma unroll
        for (int s = tid; s < 512; s += 256) {
            int mm = s >> 2, kq = (s & 3) << 2;
            float4 v = *(const float4*)&x[(size_t)(m0 + mm) * Dc + k0 + kq];
            As[kq + 0][mm] = v.x; As[kq + 1][mm] = v.y;
            As[kq + 2][mm] = v.z; As[kq + 3][mm] = v.w;
        }
        // load B tile (128 x 16) transposed -> Bs[k][n]
#pragma unroll
        for (int s = tid; s < 512; s += 256) {
            int nn = s >> 2, kq = (s & 3) << 2;
            float4 v = *(const float4*)&W[(size_t)(n0 + nn) * Dc + k0 + kq];
            Bs[kq + 0][nn] = v.x; Bs[kq + 1][nn] = v.y;
            Bs[kq + 2][nn] = v.z; Bs[kq + 3][nn] = v.w;
        }
        __syncthreads();

#pragma unroll
        for (int k = 0; k < 16; k++) {
            float a[8], b[8];
            *(float4*)&a[0] = *(const float4*)&As[k][tm];
            *(float4*)&a[4] = *(const float4*)&As[k][tm + 4];
            *(float4*)&b[0] = *(const float4*)&Bs[k][tn];
            *(float4*)&b[4] = *(const float4*)&Bs[k][tn + 4];
#pragma unroll
            for (int i = 0; i < 8; i++)
#pragma unroll
                for (int j = 0; j < 8; j++)
                    acc[i][j] = fmaf(a[i], b[j], acc[i][j]);
        }
        __syncthreads();
    }

    // epilogue: bias + scatter into q/k layouts
#pragma unroll
    for (int i = 0; i < 8; i++) {
        int m  = m0 + tm + i;
        int bb = m >> 11;          // / 2048
        int ss = m & 2047;
#pragma unroll
        for (int j = 0; j < 8; j++) {
            int n   = n0 + tn + j;
            float c = acc[i][j] + bias[n];
            int hd  = n >> 1;
            int h   = hd >> 6;
            int d   = hd & 63;
            size_t idx = ((((size_t)bb * Hc + h) * Sc + ss) * DHc + d);
            if (n & 1) g_k[idx] = c;
            else       g_q[idx] = c * 0.125f;   // fold dh^-0.5 into q
        }
    }
}

// ---------------------------------------------------------------------------
// Kernel 2: k_mean[b,h,d] = mean over s of g_k[b,h,s,d]
// ---------------------------------------------------------------------------
__global__ void kmean_kernel() {
    int idx = blockIdx.x * blockDim.x + threadIdx.x;   // 0..4095
    if (idx >= Bc * Hc * DHc) return;
    int bh = idx >> 6;
    int d  = idx & 63;
    const float* p = g_k + (size_t)bh * Sc * DHc + d;
    float s0 = 0.f, s1 = 0.f, s2 = 0.f, s3 = 0.f;
    for (int j = 0; j < Sc; j += 4) {
        s0 += p[(size_t)(j + 0) * DHc];
        s1 += p[(size_t)(j + 1) * DHc];
        s2 += p[(size_t)(j + 2) * DHc];
        s3 += p[(size_t)(j + 3) * DHc];
    }
    g_kmean[idx] = (s0 + s1 + s2 + s3) * (1.0f / (float)Sc);
}

// ---------------------------------------------------------------------------
// Kernel 3: fused attention.
//   per CTA: one (b,h), 128 query rows. Loop 64-wide j tiles:
//     sim = Qs . Ks'^T  (Ks' = k - kmean);  attn = selu(sim);  out += attn . V
//   final: out *= S^-0.5, write [B,S,H*dh]
// ---------------------------------------------------------------------------
__device__ __forceinline__ float selu_f(float v) {
    // lambda = 1.0507009873554805, lambda*alpha = 1.7580993408473766
    return v > 0.f ? 1.0507009873554805f * v
                   : 1.7580993408473766f * (expf(v) - 1.f);
}

__global__ __launch_bounds__(256, 2)
void attn_kernel(const float* __restrict__ x, float* __restrict__ out) {
    extern __shared__ float sm[];
    float* Qs = sm;                    // [64][132]  (d-major, padded)
    float* Ks = Qs + 64 * 132;         // [64][68]   (d-major)
    float* Vs = Ks + 64 * 68;          // [64][68]   (j-major)
    float* Aa = Vs + 64 * 68;          // [64][132]  (j-major attn staging)
    float* km = Aa + 64 * 132;         // [64]

    const int bh  = blockIdx.y;
    const int b   = bh >> 4;
    const int h   = bh & 15;
    const int i0  = blockIdx.x * 128;
    const int tid = threadIdx.x;
    const int ti  = tid >> 4;          // 0..15 : rows ti*8 .. ti*8+7
    const int tx  = tid & 15;          // 0..15 : cols tx*4 .. tx*4+3
    const size_t qk_base = (size_t)bh * Sc * DHc;

    // load Q tile (128 x 64) transposed -> Qs[d][i]
    for (int s = tid; s < 2048; s += 256) {
        int row = s >> 4, dq = (s & 15) << 2;
        float4 v = *(const float4*)&g_q[qk_base + (size_t)(i0 + row) * DHc + dq];
        Qs[(dq + 0) * 132 + row] = v.x;
        Qs[(dq + 1) * 132 + row] = v.y;
        Qs[(dq + 2) * 132 + row] = v.z;
        Qs[(dq + 3) * 132 + row] = v.w;
    }
    if (tid < 64) km[tid] = g_kmean[bh * 64 + tid];

    float acc[8][4];
#pragma unroll
    for (int i = 0; i < 8; i++)
#pragma unroll
        for (int j = 0; j < 4; j++) acc[i][j] = 0.f;

    for (int j0 = 0; j0 < Sc; j0 += 64) {
        __syncthreads();   // protect Ks/Vs/Aa reuse + (iter 0) Qs/km visibility

        // load K tile (64 x 64) transposed, subtracting kmean -> Ks[d][j]
        for (int s = tid; s < 1024; s += 256) {
            int row = s >> 4, dq = (s & 15) << 2;
            float4 v = *(const float4*)&g_k[qk_base + (size_t)(j0 + row) * DHc + dq];
            Ks[(dq + 0) * 68 + row] = v.x - km[dq + 0];
            Ks[(dq + 1) * 68 + row] = v.y - km[dq + 1];
            Ks[(dq + 2) * 68 + row] = v.z - km[dq + 2];
            Ks[(dq + 3) * 68 + row] = v.w - km[dq + 3];
        }
        // load V tile (64 x 64) direct from x -> Vs[j][d]
        for (int s = tid; s < 1024; s += 256) {
            int row = s >> 4, dq = (s & 15) << 2;
            float4 v = *(const float4*)&x[((size_t)b * Sc + j0 + row) * Dc + h * DHc + dq];
            *(float4*)&Vs[row * 68 + dq] = v;
        }
        __syncthreads();

        // phase 1: sim[128x64] = Q . K'^T  (inner dim d = 64)
        float simr[8][4];
#pragma unroll
        for (int i = 0; i < 8; i++)
#pragma unroll
            for (int j = 0; j < 4; j++) simr[i][j] = 0.f;

#pragma unroll 8
        for (int d = 0; d < 64; d++) {
            float a[8], bb[4];
            *(float4*)&a[0]  = *(const float4*)&Qs[d * 132 + ti * 8];
            *(float4*)&a[4]  = *(const float4*)&Qs[d * 132 + ti * 8 + 4];
            *(float4*)&bb[0] = *(const float4*)&Ks[d * 68 + tx * 4];
#pragma unroll
            for (int i = 0; i < 8; i++)
#pragma unroll
                for (int j = 0; j < 4; j++)
                    simr[i][j] = fmaf(a[i], bb[j], simr[i][j]);
        }

        // selu + stage attn to SMEM (j-major for phase-2 broadcast reads)
#pragma unroll
        for (int jj = 0; jj < 4; jj++) {
            int j = tx * 4 + jj;
            float r[8];
#pragma unroll
            for (int i = 0; i < 8; i++) r[i] = selu_f(simr[i][jj]);
            *(float4*)&Aa[j * 132 + ti * 8]     = make_float4(r[0], r[1], r[2], r[3]);
            *(float4*)&Aa[j * 132 + ti * 8 + 4] = make_float4(r[4], r[5], r[6], r[7]);
        }
        __syncthreads();

        // phase 2: out[128x64] += attn . V  (inner dim j = 64)
#pragma unroll 8
        for (int j = 0; j < 64; j++) {
            float a[8], bb[4];
            *(float4*)&a[0]  = *(const float4*)&Aa[j * 132 + ti * 8];
            *(float4*)&a[4]  = *(const float4*)&Aa[j * 132 + ti * 8 + 4];
            *(float4*)&bb[0] = *(const float4*)&Vs[j * 68 + tx * 4];
#pragma unroll
            for (int i = 0; i < 8; i++)
#pragma unroll
                for (int jd = 0; jd < 4; jd++)
                    acc[i][jd] = fmaf(a[i], bb[jd], acc[i][jd]);
        }
    }

    // write out[b][s][h*64 + d] * S^-0.5
    const float invs = 0.022097086912079608f;   // 2048^-0.5
#pragma unroll
    for (int i = 0; i < 8; i++) {
        int srow = i0 + ti * 8 + i;
        float4 o = make_float4(acc[i][0] * invs, acc[i][1] * invs,
                               acc[i][2] * invs, acc[i][3] * invs);
        *(float4*)&out[((size_t)b * Sc + srow) * Dc + h * DHc + tx * 4] = o;
    }
}

// ---------------------------------------------------------------------------
extern "C" void kernel_launch(void* const* d_in, const int* in_sizes, int n_in,
                              void* d_out, int out_size) {
    (void)in_sizes; (void)n_in; (void)out_size;
    const float* x    = (const float*)d_in[0];
    const float* W    = (const float*)d_in[1];
    const float* bias = (const float*)d_in[2];
    float* out        = (float*)d_out;

    const int smem_bytes = (64 * 132 + 64 * 68 + 64 * 68 + 64 * 132 + 64) * 4; // 102656
    cudaFuncSetAttribute((const void*)attn_kernel,
                         cudaFuncAttributeMaxDynamicSharedMemorySize, smem_bytes);

    dim3 g1(Dc * 2 / 128, (Bc * Sc) / 128);   // (16, 64)
    proj_kernel<<<g1, 256>>>(x, W, bias);

    kmean_kernel<<<(Bc * Hc * DHc + 255) / 256, 256>>>();

    dim3 g3(Sc / 128, Bc * Hc);               // (16, 64)
    attn_kernel<<<g3, 256, smem_bytes>>>(x, out);
}

// round 16
// speedup vs baseline: 1.2192x; 1.2192x over previous
#include <cuda_runtime.h>
#include <cuda_bf16.h>
#include <stdint.h>
#include <math.h>

// Problem constants
#define Bc  4
#define Hc  16
#define Sc  2048
#define Dc  1024
#define DHc 64

// Scratch (device globals: allowed; no runtime allocation)
__device__ __align__(16) __nv_bfloat16 g_qh[(size_t)Bc * Hc * Sc * DHc];
__device__ __align__(16) __nv_bfloat16 g_ql[(size_t)Bc * Hc * Sc * DHc];
__device__ __align__(16) __nv_bfloat16 g_kh[(size_t)Bc * Hc * Sc * DHc];
__device__ __align__(16) __nv_bfloat16 g_kl[(size_t)Bc * Hc * Sc * DHc];
__device__ float g_kmean[Bc * Hc * DHc];

// ---------------------------------------------------------------------------
// mma.sync helper (sm_80+, legal on base compute_103 target)
// ---------------------------------------------------------------------------
__device__ __forceinline__ void mma16816(float* c, const uint32_t* a, const uint32_t* b) {
    asm volatile(
        "mma.sync.aligned.m16n8k16.row.col.f32.bf16.bf16.f32 "
        "{%0,%1,%2,%3}, {%4,%5,%6,%7}, {%8,%9}, {%0,%1,%2,%3};"
        : "+f"(c[0]), "+f"(c[1]), "+f"(c[2]), "+f"(c[3])
        : "r"(a[0]), "r"(a[1]), "r"(a[2]), "r"(a[3]), "r"(b[0]), "r"(b[1]));
}

// pack (a -> low half, b -> high half) as bf16x2, plus residual pack
__device__ __forceinline__ void split2(float a, float b, uint32_t& hi, uint32_t& lo) {
    __nv_bfloat16 ha = __float2bfloat16(a), hb = __float2bfloat16(b);
    __nv_bfloat162 H = __halves2bfloat162(ha, hb);
    __nv_bfloat162 L = __halves2bfloat162(
        __float2bfloat16(a - __bfloat162float(ha)),
        __float2bfloat16(b - __bfloat162float(hb)));
    hi = *(uint32_t*)&H;
    lo = *(uint32_t*)&L;
}

__device__ __forceinline__ float selu_f(float v) {
    return v > 0.f ? 1.0507009873554805f * v
                   : 1.7580993408473766f * (__expf(v) - 1.f);
}

// ---------------------------------------------------------------------------
// Kernel 1: fused q/k projection; epilogue writes bf16 hi/lo splits
// ---------------------------------------------------------------------------
__global__ __launch_bounds__(256, 2)
void proj_kernel(const float* __restrict__ x, const float* __restrict__ W,
                 const float* __restrict__ bias) {
    __shared__ float As[16][132];
    __shared__ float Bs[16][132];

    const int m0  = blockIdx.y * 128;
    const int n0  = blockIdx.x * 128;
    const int tid = threadIdx.x;
    const int tm  = (tid >> 4) * 8;
    const int tn  = (tid & 15) * 8;

    float acc[8][8];
#pragma unroll
    for (int i = 0; i < 8; i++)
#pragma unroll
        for (int j = 0; j < 8; j++) acc[i][j] = 0.f;

    for (int k0 = 0; k0 < Dc; k0 += 16) {
#pragma unroll
        for (int s = tid; s < 512; s += 256) {
            int mm = s >> 2, kq = (s & 3) << 2;
            float4 v = *(const float4*)&x[(size_t)(m0 + mm) * Dc + k0 + kq];
            As[kq + 0][mm] = v.x; As[kq + 1][mm] = v.y;
            As[kq + 2][mm] = v.z; As[kq + 3][mm] = v.w;
        }
#pragma unroll
        for (int s = tid; s < 512; s += 256) {
            int nn = s >> 2, kq = (s & 3) << 2;
            float4 v = *(const float4*)&W[(size_t)(n0 + nn) * Dc + k0 + kq];
            Bs[kq + 0][nn] = v.x; Bs[kq + 1][nn] = v.y;
            Bs[kq + 2][nn] = v.z; Bs[kq + 3][nn] = v.w;
        }
        __syncthreads();

#pragma unroll
        for (int k = 0; k < 16; k++) {
            float a[8], b[8];
            *(float4*)&a[0] = *(const float4*)&As[k][tm];
            *(float4*)&a[4] = *(const float4*)&As[k][tm + 4];
            *(float4*)&b[0] = *(const float4*)&Bs[k][tn];
            *(float4*)&b[4] = *(const float4*)&Bs[k][tn + 4];
#pragma unroll
            for (int i = 0; i < 8; i++)
#pragma unroll
                for (int j = 0; j < 8; j++)
                    acc[i][j] = fmaf(a[i], b[j], acc[i][j]);
        }
        __syncthreads();
    }

#pragma unroll
    for (int i = 0; i < 8; i++) {
        int m  = m0 + tm + i;
        int bb = m >> 11;
        int ss = m & 2047;
#pragma unroll
        for (int j = 0; j < 8; j++) {
            int n   = n0 + tn + j;
            float c = acc[i][j] + bias[n];
            int hd  = n >> 1;
            int hh  = hd >> 6;
            int dd  = hd & 63;
            size_t idx = ((((size_t)bb * Hc + hh) * Sc + ss) * DHc + dd);
            if (n & 1) {
                __nv_bfloat16 hi = __float2bfloat16(c);
                g_kh[idx] = hi;
                g_kl[idx] = __float2bfloat16(c - __bfloat162float(hi));
            } else {
                c *= 0.125f;    // fold dh^-0.5 into q
                __nv_bfloat16 hi = __float2bfloat16(c);
                g_qh[idx] = hi;
                g_ql[idx] = __float2bfloat16(c - __bfloat162float(hi));
            }
        }
    }
}

// ---------------------------------------------------------------------------
// Kernel 2: k_mean[b,h,d] = mean over s of (k_hi + k_lo)
// ---------------------------------------------------------------------------
__global__ void kmean_kernel() {
    int idx = blockIdx.x * blockDim.x + threadIdx.x;
    if (idx >= Bc * Hc * DHc) return;
    int bh = idx >> 6;
    int d  = idx & 63;
    const __nv_bfloat16* ph = g_kh + (size_t)bh * Sc * DHc + d;
    const __nv_bfloat16* pl = g_kl + (size_t)bh * Sc * DHc + d;
    float s0 = 0.f, s1 = 0.f;
    for (int j = 0; j < Sc; j += 2) {
        s0 += __bfloat162float(ph[(size_t)j * DHc]) + __bfloat162float(pl[(size_t)j * DHc]);
        s1 += __bfloat162float(ph[(size_t)(j + 1) * DHc]) + __bfloat162float(pl[(size_t)(j + 1) * DHc]);
    }
    g_kmean[idx] = (s0 + s1) * (1.0f / (float)Sc);
}

// ---------------------------------------------------------------------------
// Kernel 3: mma.sync attention. Per CTA: one (b,h), 128 q rows, 8 warps.
//   warp w owns rows [w*16, w*16+16). Q frags persistent in registers.
//   3-term bf16 hi/lo split on both GEMMs.
//   Mean subtraction done ONCE: K' = k - kmean at staging (no ci term).
// ---------------------------------------------------------------------------
#define JT   64          // j-tile width
#define KSTR 72          // staged row stride in bf16 elems (conflict-free)

__global__ __launch_bounds__(256)
void attn_kernel(const float* __restrict__ x, float* __restrict__ out) {
    __shared__ __nv_bfloat16 Ksh[64 * KSTR], Ksl[64 * KSTR];
    __shared__ __nv_bfloat16 Vth[64 * KSTR], Vtl[64 * KSTR];
    __shared__ float km[64];

    const int tid  = threadIdx.x;
    const int w    = tid >> 5;
    const int lane = tid & 31;
    const int g    = lane >> 2;    // group row 0..7
    const int q4   = lane & 3;     // quad col 0..3
    const int bh   = blockIdx.y;
    const int b    = bh >> 4;
    const int h    = bh & 15;
    const int i0   = blockIdx.x * 128;
    const size_t qk = (size_t)bh * Sc * DHc;

    if (tid < 64) km[tid] = g_kmean[bh * 64 + tid];

    // --- persistent Q fragments (hi/lo), 4 k-tiles of d ---
    uint32_t Qh[4][4], Ql[4][4];
    {
        const __nv_bfloat16* qhp = g_qh + qk + (size_t)(i0 + w * 16 + g) * DHc;
        const __nv_bfloat16* qlp = g_ql + qk + (size_t)(i0 + w * 16 + g) * DHc;
#pragma unroll
        for (int kt = 0; kt < 4; kt++) {
            int d = kt * 16 + q4 * 2;
            Qh[kt][0] = *(const uint32_t*)(qhp + d);
            Qh[kt][1] = *(const uint32_t*)(qhp + 8 * DHc + d);
            Qh[kt][2] = *(const uint32_t*)(qhp + d + 8);
            Qh[kt][3] = *(const uint32_t*)(qhp + 8 * DHc + d + 8);
            Ql[kt][0] = *(const uint32_t*)(qlp + d);
            Ql[kt][1] = *(const uint32_t*)(qlp + 8 * DHc + d);
            Ql[kt][2] = *(const uint32_t*)(qlp + d + 8);
            Ql[kt][3] = *(const uint32_t*)(qlp + 8 * DHc + d + 8);
        }
    }
    __syncthreads();

    float acc[8][4];
#pragma unroll
    for (int i = 0; i < 8; i++)
#pragma unroll
        for (int j = 0; j < 4; j++) acc[i][j] = 0.f;

    for (int t = 0; t < 32; t++) {
        const int j0 = t * JT;
        if (t > 0) __syncthreads();   // previous iteration's readers done

        // --- stage K' = k - kmean (hi/lo), row-major [j][d] ---
        {
            const int j  = tid >> 2;
            const int d0 = (tid & 3) << 4;
            const __nv_bfloat16* kh = g_kh + qk + (size_t)(j0 + j) * DHc + d0;
            const __nv_bfloat16* kl = g_kl + qk + (size_t)(j0 + j) * DHc + d0;
            __nv_bfloat16 hb[16], lb[16];
            *(uint4*)&hb[0] = *(const uint4*)kh;
            *(uint4*)&hb[8] = *(const uint4*)(kh + 8);
            *(uint4*)&lb[0] = *(const uint4*)kl;
            *(uint4*)&lb[8] = *(const uint4*)(kl + 8);
#pragma unroll
            for (int e = 0; e < 16; e += 2) {
                float f0 = __bfloat162float(hb[e])     + __bfloat162float(lb[e])     - km[d0 + e];
                float f1 = __bfloat162float(hb[e + 1]) + __bfloat162float(lb[e + 1]) - km[d0 + e + 1];
                uint32_t phi, plo;
                split2(f0, f1, phi, plo);
                *(uint32_t*)&Ksh[j * KSTR + d0 + e] = phi;
                *(uint32_t*)&Ksl[j * KSTR + d0 + e] = plo;
            }
            // --- stage V^T (hi/lo), [d][j], split from x ---
            const float* xr = x + ((size_t)b * Sc + j0 + j) * Dc + h * DHc + d0;
#pragma unroll
            for (int e4 = 0; e4 < 16; e4 += 4) {
                float4 v = *(const float4*)(xr + e4);
                float vv[4] = {v.x, v.y, v.z, v.w};
#pragma unroll
                for (int u = 0; u < 4; u++) {
                    int d = d0 + e4 + u;
                    __nv_bfloat16 hi = __float2bfloat16(vv[u]);
                    Vth[d * KSTR + j] = hi;
                    Vtl[d * KSTR + j] = __float2bfloat16(vv[u] - __bfloat162float(hi));
                }
            }
        }
        __syncthreads();

        // --- phase 1: sim = Q . K'^T  (3 split terms, 8 independent accs) ---
        float C[8][4];
#pragma unroll
        for (int i = 0; i < 8; i++)
#pragma unroll
            for (int j = 0; j < 4; j++) C[i][j] = 0.f;

#pragma unroll
        for (int kt = 0; kt < 4; kt++) {
            const int dd = kt * 16 + q4 * 2;
#pragma unroll
            for (int nt = 0; nt < 8; nt++) {
                const int jj = nt * 8 + g;
                uint32_t bb[2];
                bb[0] = *(const uint32_t*)&Ksh[jj * KSTR + dd];
                bb[1] = *(const uint32_t*)&Ksh[jj * KSTR + dd + 8];
                mma16816(C[nt], Qh[kt], bb);
            }
#pragma unroll
            for (int nt = 0; nt < 8; nt++) {
                const int jj = nt * 8 + g;
                uint32_t bb[2];
                bb[0] = *(const uint32_t*)&Ksl[jj * KSTR + dd];
                bb[1] = *(const uint32_t*)&Ksl[jj * KSTR + dd + 8];
                mma16816(C[nt], Qh[kt], bb);
            }
#pragma unroll
            for (int nt = 0; nt < 8; nt++) {
                const int jj = nt * 8 + g;
                uint32_t bb[2];
                bb[0] = *(const uint32_t*)&Ksh[jj * KSTR + dd];
                bb[1] = *(const uint32_t*)&Ksh[jj * KSTR + dd + 8];
                mma16816(C[nt], Ql[kt], bb);
            }
        }

        // --- selu(sim) in registers (mean already removed via K') ---
#pragma unroll
        for (int nt = 0; nt < 8; nt++) {
            C[nt][0] = selu_f(C[nt][0]);
            C[nt][1] = selu_f(C[nt][1]);
            C[nt][2] = selu_f(C[nt][2]);
            C[nt][3] = selu_f(C[nt][3]);
        }

        // --- phase 2: out += attn . V  (C frags repacked as A frags) ---
#pragma unroll
        for (int ktj = 0; ktj < 4; ktj++) {
            uint32_t Ah[4], Al[4];
            split2(C[2 * ktj][0],     C[2 * ktj][1],     Ah[0], Al[0]);
            split2(C[2 * ktj][2],     C[2 * ktj][3],     Ah[1], Al[1]);
            split2(C[2 * ktj + 1][0], C[2 * ktj + 1][1], Ah[2], Al[2]);
            split2(C[2 * ktj + 1][2], C[2 * ktj + 1][3], Ah[3], Al[3]);
            const int jj = ktj * 16 + q4 * 2;
#pragma unroll
            for (int ntd = 0; ntd < 8; ntd++) {
                const int dd = ntd * 8 + g;
                uint32_t bb[2];
                bb[0] = *(const uint32_t*)&Vth[dd * KSTR + jj];
                bb[1] = *(const uint32_t*)&Vth[dd * KSTR + jj + 8];
                mma16816(acc[ntd], Ah, bb);
            }
#pragma unroll
            for (int ntd = 0; ntd < 8; ntd++) {
                const int dd = ntd * 8 + g;
                uint32_t bb[2];
                bb[0] = *(const uint32_t*)&Vtl[dd * KSTR + jj];
                bb[1] = *(const uint32_t*)&Vtl[dd * KSTR + jj + 8];
                mma16816(acc[ntd], Ah, bb);
            }
#pragma unroll
            for (int ntd = 0; ntd < 8; ntd++) {
                const int dd = ntd * 8 + g;
                uint32_t bb[2];
                bb[0] = *(const uint32_t*)&Vth[dd * KSTR + jj];
                bb[1] = *(const uint32_t*)&Vth[dd * KSTR + jj + 8];
                mma16816(acc[ntd], Al, bb);
            }
        }
    }

    // --- epilogue: out * S^-0.5 -> [b][s][h*64+d] ---
    const float invs = 0.022097086912079608f;   // 2048^-0.5
    float* o0 = out + ((size_t)b * Sc + i0 + w * 16 + g) * Dc + h * DHc;
    float* o1 = o0 + 8 * Dc;
#pragma unroll
    for (int nt = 0; nt < 8; nt++) {
        const int d = nt * 8 + q4 * 2;
        *(float2*)(o0 + d) = make_float2(acc[nt][0] * invs, acc[nt][1] * invs);
        *(float2*)(o1 + d) = make_float2(acc[nt][2] * invs, acc[nt][3] * invs);
    }
}

// ---------------------------------------------------------------------------
extern "C" void kernel_launch(void* const* d_in, const int* in_sizes, int n_in,
                              void* d_out, int out_size) {
    (void)in_sizes; (void)n_in; (void)out_size;
    const float* x    = (const float*)d_in[0];
    const float* W    = (const float*)d_in[1];
    const float* bias = (const float*)d_in[2];
    float* out        = (float*)d_out;

    dim3 g1(Dc * 2 / 128, (Bc * Sc) / 128);   // (16, 64)
    proj_kernel<<<g1, 256>>>(x, W, bias);

    kmean_kernel<<<(Bc * Hc * DHc + 255) / 256, 256>>>();

    dim3 g3(Sc / 128, Bc * Hc);               // (16, 64)
    attn_kernel<<<g3, 256>>>(x, out);
}

// round 17
// speedup vs baseline: 1.5303x; 1.2552x over previous
#include <cuda_runtime.h>
#include <cuda_bf16.h>
#include <stdint.h>
#include <math.h>

// Problem constants
#define Bc  4
#define Hc  16
#define Sc  2048
#define Dc  1024
#define DHc 64

// Scratch (device globals: allowed; no runtime allocation)
__device__ __align__(16) __nv_bfloat16 g_qh[(size_t)Bc * Hc * Sc * DHc];
__device__ __align__(16) __nv_bfloat16 g_ql[(size_t)Bc * Hc * Sc * DHc];
__device__ __align__(16) __nv_bfloat16 g_kh[(size_t)Bc * Hc * Sc * DHc];
__device__ __align__(16) __nv_bfloat16 g_kl[(size_t)Bc * Hc * Sc * DHc];
__device__ __align__(16) __nv_bfloat16 g_xh[(size_t)Bc * Sc * Dc];   // x split (also V source)
__device__ __align__(16) __nv_bfloat16 g_xl[(size_t)Bc * Sc * Dc];
__device__ __align__(16) __nv_bfloat16 g_wh[(size_t)2 * Dc * Dc];    // W split
__device__ __align__(16) __nv_bfloat16 g_wl[(size_t)2 * Dc * Dc];
__device__ float g_kmean[Bc * Hc * DHc];

// ---------------------------------------------------------------------------
// mma.sync helper (sm_80+, legal on base compute_103 target)
// ---------------------------------------------------------------------------
__device__ __forceinline__ void mma16816(float* c, const uint32_t* a, const uint32_t* b) {
    asm volatile(
        "mma.sync.aligned.m16n8k16.row.col.f32.bf16.bf16.f32 "
        "{%0,%1,%2,%3}, {%4,%5,%6,%7}, {%8,%9}, {%0,%1,%2,%3};"
        : "+f"(c[0]), "+f"(c[1]), "+f"(c[2]), "+f"(c[3])
        : "r"(a[0]), "r"(a[1]), "r"(a[2]), "r"(a[3]), "r"(b[0]), "r"(b[1]));
}

// pack (a -> low half, b -> high half) as bf16x2, plus residual pack
__device__ __forceinline__ void split2(float a, float b, uint32_t& hi, uint32_t& lo) {
    __nv_bfloat16 ha = __float2bfloat16(a), hb = __float2bfloat16(b);
    __nv_bfloat162 H = __halves2bfloat162(ha, hb);
    __nv_bfloat162 L = __halves2bfloat162(
        __float2bfloat16(a - __bfloat162float(ha)),
        __float2bfloat16(b - __bfloat162float(hb)));
    hi = *(uint32_t*)&H;
    lo = *(uint32_t*)&L;
}

__device__ __forceinline__ float selu_f(float v) {
    return v > 0.f ? 1.0507009873554805f * v
                   : 1.7580993408473766f * (__expf(v) - 1.f);
}

// ---------------------------------------------------------------------------
// Prep kernels: global hi/lo splits (once, memory-bound)
// ---------------------------------------------------------------------------
__global__ void split_x_kernel(const float* __restrict__ x) {
    size_t i4 = ((size_t)blockIdx.x * blockDim.x + threadIdx.x) * 4;
    float4 v = *(const float4*)(x + i4);
    uint32_t h0, l0, h1, l1;
    split2(v.x, v.y, h0, l0);
    split2(v.z, v.w, h1, l1);
    *(uint2*)(g_xh + i4) = make_uint2(h0, h1);
    *(uint2*)(g_xl + i4) = make_uint2(l0, l1);
}

__global__ void split_w_kernel(const float* __restrict__ W) {
    size_t i4 = ((size_t)blockIdx.x * blockDim.x + threadIdx.x) * 4;
    float4 v = *(const float4*)(W + i4);
    uint32_t h0, l0, h1, l1;
    split2(v.x, v.y, h0, l0);
    split2(v.z, v.w, h1, l1);
    *(uint2*)(g_wh + i4) = make_uint2(h0, h1);
    *(uint2*)(g_wl + i4) = make_uint2(l0, l1);
}

// ---------------------------------------------------------------------------
// Kernel: fused q/k projection via mma.sync bf16 3-term split.
//   C[m,n] = x[m,:] . W[n,:] + bias[n];  CTA tile 128(M) x 64(N), KC=64.
//   8 warps = 4(M) x 2(N); warp tile 32x32.
// ---------------------------------------------------------------------------
#define PSTR 72
#define PROJ_SMEM ((2 * 128 * PSTR + 2 * 64 * PSTR) * 2)   // 55296 bytes

__global__ __launch_bounds__(256, 2)
void proj_mma_kernel(const float* __restrict__ bias) {
    extern __shared__ __nv_bfloat16 psm[];
    __nv_bfloat16* Ash = psm;                    // [128][72]
    __nv_bfloat16* Asl = Ash + 128 * PSTR;
    __nv_bfloat16* Bsh = Asl + 128 * PSTR;       // [64][72]
    __nv_bfloat16* Bsl = Bsh + 64 * PSTR;

    const int m0   = blockIdx.y * 128;
    const int n0   = blockIdx.x * 64;
    const int tid  = threadIdx.x;
    const int w    = tid >> 5;
    const int lane = tid & 31;
    const int g    = lane >> 2;
    const int q4   = lane & 3;
    const int wm   = (w >> 1) * 32;
    const int wn   = (w & 1) * 32;

    float acc[2][4][4];
#pragma unroll
    for (int mi = 0; mi < 2; mi++)
#pragma unroll
        for (int ni = 0; ni < 4; ni++)
#pragma unroll
            for (int c = 0; c < 4; c++) acc[mi][ni][c] = 0.f;

    for (int kc = 0; kc < 16; kc++) {
        const int k0 = kc * 64;
        if (kc > 0) __syncthreads();
        // stage A (x split): 128 rows x 64 cols; thread: row=tid>>1, 32 cols
        {
            const int row = tid >> 1, cs = (tid & 1) * 32;
            const uint4* sh = (const uint4*)(g_xh + (size_t)(m0 + row) * Dc + k0 + cs);
            const uint4* sl = (const uint4*)(g_xl + (size_t)(m0 + row) * Dc + k0 + cs);
            uint4* dh = (uint4*)&Ash[row * PSTR + cs];
            uint4* dl = (uint4*)&Asl[row * PSTR + cs];
#pragma unroll
            for (int u = 0; u < 4; u++) { dh[u] = sh[u]; dl[u] = sl[u]; }
        }
        // stage B (W split): 64 rows x 64 cols; thread: row=tid>>2, 16 cols
        {
            const int row = tid >> 2, cs = (tid & 3) * 16;
            const uint4* sh = (const uint4*)(g_wh + (size_t)(n0 + row) * Dc + k0 + cs);
            const uint4* sl = (const uint4*)(g_wl + (size_t)(n0 + row) * Dc + k0 + cs);
            uint4* dh = (uint4*)&Bsh[row * PSTR + cs];
            uint4* dl = (uint4*)&Bsl[row * PSTR + cs];
            dh[0] = sh[0]; dh[1] = sh[1]; dl[0] = sl[0]; dl[1] = sl[1];
        }
        __syncthreads();

#pragma unroll
        for (int kt = 0; kt < 4; kt++) {
            const int dd = kt * 16 + q4 * 2;
            uint32_t Ah[2][4], Al[2][4];
#pragma unroll
            for (int mi = 0; mi < 2; mi++) {
                const __nv_bfloat16* ar = &Ash[(wm + mi * 16 + g) * PSTR];
                const __nv_bfloat16* al = &Asl[(wm + mi * 16 + g) * PSTR];
                Ah[mi][0] = *(const uint32_t*)(ar + dd);
                Ah[mi][1] = *(const uint32_t*)(ar + 8 * PSTR + dd);
                Ah[mi][2] = *(const uint32_t*)(ar + dd + 8);
                Ah[mi][3] = *(const uint32_t*)(ar + 8 * PSTR + dd + 8);
                Al[mi][0] = *(const uint32_t*)(al + dd);
                Al[mi][1] = *(const uint32_t*)(al + 8 * PSTR + dd);
                Al[mi][2] = *(const uint32_t*)(al + dd + 8);
                Al[mi][3] = *(const uint32_t*)(al + 8 * PSTR + dd + 8);
            }
#pragma unroll
            for (int ni = 0; ni < 4; ni++) {
                const __nv_bfloat16* br = &Bsh[(wn + ni * 8 + g) * PSTR];
                uint32_t bb[2];
                bb[0] = *(const uint32_t*)(br + dd);
                bb[1] = *(const uint32_t*)(br + dd + 8);
                mma16816(acc[0][ni], Ah[0], bb);
                mma16816(acc[0][ni], Al[0], bb);
                mma16816(acc[1][ni], Ah[1], bb);
                mma16816(acc[1][ni], Al[1], bb);
            }
#pragma unroll
            for (int ni = 0; ni < 4; ni++) {
                const __nv_bfloat16* br = &Bsl[(wn + ni * 8 + g) * PSTR];
                uint32_t bb[2];
                bb[0] = *(const uint32_t*)(br + dd);
                bb[1] = *(const uint32_t*)(br + dd + 8);
                mma16816(acc[0][ni], Ah[0], bb);
                mma16816(acc[1][ni], Ah[1], bb);
            }
        }
    }

    // epilogue: bias + scatter q/k hi-lo splits.  col n even -> q, n+1 -> k (same hd)
#pragma unroll
    for (int mi = 0; mi < 2; mi++) {
        const int mrow0 = m0 + wm + mi * 16 + g;
#pragma unroll
        for (int ni = 0; ni < 4; ni++) {
            const int n  = n0 + wn + ni * 8 + q4 * 2;     // even
            const float bq = __ldg(bias + n);
            const float bk = __ldg(bias + n + 1);
            const int hd = n >> 1, hh = hd >> 6, dd2 = hd & 63;
#pragma unroll
            for (int r = 0; r < 2; r++) {
                const int m  = mrow0 + r * 8;
                const int b_ = m >> 11, s_ = m & 2047;
                const size_t idx = ((((size_t)b_ * Hc + hh) * Sc + s_) * DHc + dd2);
                float qv = (acc[mi][ni][2 * r] + bq) * 0.125f;
                float kv =  acc[mi][ni][2 * r + 1] + bk;
                __nv_bfloat16 qh = __float2bfloat16(qv);
                g_qh[idx] = qh;
                g_ql[idx] = __float2bfloat16(qv - __bfloat162float(qh));
                __nv_bfloat16 kh = __float2bfloat16(kv);
                g_kh[idx] = kh;
                g_kl[idx] = __float2bfloat16(kv - __bfloat162float(kh));
            }
        }
    }
}

// ---------------------------------------------------------------------------
// kmean: k_mean[b,h,d] = mean over s of (k_hi + k_lo)
// ---------------------------------------------------------------------------
__global__ void kmean_kernel() {
    int idx = blockIdx.x * blockDim.x + threadIdx.x;
    if (idx >= Bc * Hc * DHc) return;
    int bh = idx >> 6;
    int d  = idx & 63;
    const __nv_bfloat16* ph = g_kh + (size_t)bh * Sc * DHc + d;
    const __nv_bfloat16* pl = g_kl + (size_t)bh * Sc * DHc + d;
    float s0 = 0.f, s1 = 0.f;
    for (int j = 0; j < Sc; j += 2) {
        s0 += __bfloat162float(ph[(size_t)j * DHc]) + __bfloat162float(pl[(size_t)j * DHc]);
        s1 += __bfloat162float(ph[(size_t)(j + 1) * DHc]) + __bfloat162float(pl[(size_t)(j + 1) * DHc]);
    }
    g_kmean[idx] = (s0 + s1) * (1.0f / (float)Sc);
}

// ---------------------------------------------------------------------------
// prep_k: in-place K' = split(k - kmean). Each thread owns 2 elems (d even).
// ---------------------------------------------------------------------------
__global__ void prep_k_kernel() {
    size_t i2 = ((size_t)blockIdx.x * blockDim.x + threadIdx.x) * 2;
    int d  = (int)(i2 & 63);
    int bh = (int)(i2 >> 17);          // Sc*DHc = 131072 = 2^17
    float km0 = g_kmean[bh * 64 + d];
    float km1 = g_kmean[bh * 64 + d + 1];
    float f0 = __bfloat162float(g_kh[i2])     + __bfloat162float(g_kl[i2])     - km0;
    float f1 = __bfloat162float(g_kh[i2 + 1]) + __bfloat162float(g_kl[i2 + 1]) - km1;
    uint32_t hi, lo;
    split2(f0, f1, hi, lo);
    *(uint32_t*)(g_kh + i2) = hi;
    *(uint32_t*)(g_kl + i2) = lo;
}

// ---------------------------------------------------------------------------
// Attention: mma.sync, per CTA one (b,h) x 128 q-rows, 8 warps.
//   Staging is pure copies (K' and V splits precomputed globally).
// ---------------------------------------------------------------------------
#define KSTR 72

__global__ __launch_bounds__(256)
void attn_kernel(float* __restrict__ out) {
    __shared__ __nv_bfloat16 Ksh[64 * KSTR], Ksl[64 * KSTR];
    __shared__ __nv_bfloat16 Vth[64 * KSTR], Vtl[64 * KSTR];

    const int tid  = threadIdx.x;
    const int w    = tid >> 5;
    const int lane = tid & 31;
    const int g    = lane >> 2;
    const int q4   = lane & 3;
    const int bh   = blockIdx.y;
    const int b    = bh >> 4;
    const int h    = bh & 15;
    const int i0   = blockIdx.x * 128;
    const size_t qk = (size_t)bh * Sc * DHc;

    // --- persistent Q fragments (hi/lo), 4 k-tiles of d ---
    uint32_t Qh[4][4], Ql[4][4];
    {
        const __nv_bfloat16* qhp = g_qh + qk + (size_t)(i0 + w * 16 + g) * DHc;
        const __nv_bfloat16* qlp = g_ql + qk + (size_t)(i0 + w * 16 + g) * DHc;
#pragma unroll
        for (int kt = 0; kt < 4; kt++) {
            int d = kt * 16 + q4 * 2;
            Qh[kt][0] = *(const uint32_t*)(qhp + d);
            Qh[kt][1] = *(const uint32_t*)(qhp + 8 * DHc + d);
            Qh[kt][2] = *(const uint32_t*)(qhp + d + 8);
            Qh[kt][3] = *(const uint32_t*)(qhp + 8 * DHc + d + 8);
            Ql[kt][0] = *(const uint32_t*)(qlp + d);
            Ql[kt][1] = *(const uint32_t*)(qlp + 8 * DHc + d);
            Ql[kt][2] = *(const uint32_t*)(qlp + d + 8);
            Ql[kt][3] = *(const uint32_t*)(qlp + 8 * DHc + d + 8);
        }
    }

    float acc[8][4];
#pragma unroll
    for (int i = 0; i < 8; i++)
#pragma unroll
        for (int j = 0; j < 4; j++) acc[i][j] = 0.f;

    for (int t = 0; t < 32; t++) {
        const int j0 = t * 64;
        if (t > 0) __syncthreads();

        // --- stage K' tile (pure copy) ---
        {
            const int j  = tid >> 2;
            const int d0 = (tid & 3) << 4;
            const uint4* sh = (const uint4*)(g_kh + qk + (size_t)(j0 + j) * DHc + d0);
            const uint4* sl = (const uint4*)(g_kl + qk + (size_t)(j0 + j) * DHc + d0);
            *(uint4*)&Ksh[j * KSTR + d0]     = sh[0];
            *(uint4*)&Ksh[j * KSTR + d0 + 8] = sh[1];
            *(uint4*)&Ksl[j * KSTR + d0]     = sl[0];
            *(uint4*)&Ksl[j * KSTR + d0 + 8] = sl[1];

            // --- stage V^T tile from global x split (copy + transpose) ---
            const size_t xo = ((size_t)b * Sc + j0 + j) * Dc + h * DHc + d0;
            uint4 vh0 = *(const uint4*)(g_xh + xo);
            uint4 vh1 = *(const uint4*)(g_xh + xo + 8);
            uint4 vl0 = *(const uint4*)(g_xl + xo);
            uint4 vl1 = *(const uint4*)(g_xl + xo + 8);
            const __nv_bfloat16* eh = (const __nv_bfloat16*)&vh0;
            const __nv_bfloat16* el = (const __nv_bfloat16*)&vl0;
#pragma unroll
            for (int u = 0; u < 8; u++) {
                Vth[(d0 + u) * KSTR + j] = eh[u];
                Vtl[(d0 + u) * KSTR + j] = el[u];
            }
            eh = (const __nv_bfloat16*)&vh1;
            el = (const __nv_bfloat16*)&vl1;
#pragma unroll
            for (int u = 0; u < 8; u++) {
                Vth[(d0 + 8 + u) * KSTR + j] = eh[u];
                Vtl[(d0 + 8 + u) * KSTR + j] = el[u];
            }
        }
        __syncthreads();

        // --- phase 1: sim = Q . K'^T  (3 split terms, shared B-frags) ---
        float C[8][4];
#pragma unroll
        for (int i = 0; i < 8; i++)
#pragma unroll
            for (int j = 0; j < 4; j++) C[i][j] = 0.f;

#pragma unroll
        for (int kt = 0; kt < 4; kt++) {
            const int dd = kt * 16 + q4 * 2;
#pragma unroll
            for (int nt = 0; nt < 8; nt++) {
                const int jj = nt * 8 + g;
                uint32_t bb[2];
                bb[0] = *(const uint32_t*)&Ksh[jj * KSTR + dd];
                bb[1] = *(const uint32_t*)&Ksh[jj * KSTR + dd + 8];
                mma16816(C[nt], Qh[kt], bb);
                mma16816(C[nt], Ql[kt], bb);
            }
#pragma unroll
            for (int nt = 0; nt < 8; nt++) {
                const int jj = nt * 8 + g;
                uint32_t bb[2];
                bb[0] = *(const uint32_t*)&Ksl[jj * KSTR + dd];
                bb[1] = *(const uint32_t*)&Ksl[jj * KSTR + dd + 8];
                mma16816(C[nt], Qh[kt], bb);
            }
        }

        // --- selu in registers ---
#pragma unroll
        for (int nt = 0; nt < 8; nt++) {
            C[nt][0] = selu_f(C[nt][0]);
            C[nt][1] = selu_f(C[nt][1]);
            C[nt][2] = selu_f(C[nt][2]);
            C[nt][3] = selu_f(C[nt][3]);
        }

        // --- phase 2: out += attn . V  (C frags repacked as A frags) ---
#pragma unroll
        for (int ktj = 0; ktj < 4; ktj++) {
            uint32_t Ah[4], Al[4];
            split2(C[2 * ktj][0],     C[2 * ktj][1],     Ah[0], Al[0]);
            split2(C[2 * ktj][2],     C[2 * ktj][3],     Ah[1], Al[1]);
            split2(C[2 * ktj + 1][0], C[2 * ktj + 1][1], Ah[2], Al[2]);
            split2(C[2 * ktj + 1][2], C[2 * ktj + 1][3], Ah[3], Al[3]);
            const int jj = ktj * 16 + q4 * 2;
#pragma unroll
            for (int ntd = 0; ntd < 8; ntd++) {
                const int dd = ntd * 8 + g;
                uint32_t bb[2];
                bb[0] = *(const uint32_t*)&Vth[dd * KSTR + jj];
                bb[1] = *(const uint32_t*)&Vth[dd * KSTR + jj + 8];
                mma16816(acc[ntd], Ah, bb);
                mma16816(acc[ntd], Al, bb);
            }
#pragma unroll
            for (int ntd = 0; ntd < 8; ntd++) {
                const int dd = ntd * 8 + g;
                uint32_t bb[2];
                bb[0] = *(const uint32_t*)&Vtl[dd * KSTR + jj];
                bb[1] = *(const uint32_t*)&Vtl[dd * KSTR + jj + 8];
                mma16816(acc[ntd], Ah, bb);
            }
        }
    }

    // --- epilogue: out * S^-0.5 -> [b][s][h*64+d] ---
    const float invs = 0.022097086912079608f;   // 2048^-0.5
    float* o0 = out + ((size_t)b * Sc + i0 + w * 16 + g) * Dc + h * DHc;
    float* o1 = o0 + 8 * Dc;
#pragma unroll
    for (int nt = 0; nt < 8; nt++) {
        const int d = nt * 8 + q4 * 2;
        *(float2*)(o0 + d) = make_float2(acc[nt][0] * invs, acc[nt][1] * invs);
        *(float2*)(o1 + d) = make_float2(acc[nt][2] * invs, acc[nt][3] * invs);
    }
}

// ---------------------------------------------------------------------------
extern "C" void kernel_launch(void* const* d_in, const int* in_sizes, int n_in,
                              void* d_out, int out_size) {
    (void)in_sizes; (void)n_in; (void)out_size;
    const float* x    = (const float*)d_in[0];
    const float* W    = (const float*)d_in[1];
    const float* bias = (const float*)d_in[2];
    float* out        = (float*)d_out;

    cudaFuncSetAttribute((const void*)proj_mma_kernel,
                         cudaFuncAttributeMaxDynamicSharedMemorySize, PROJ_SMEM);

    split_x_kernel<<<(Bc * Sc * Dc) / (256 * 4), 256>>>(x);        // 8192 blocks
    split_w_kernel<<<(2 * Dc * Dc) / (256 * 4), 256>>>(W);         // 2048 blocks

    dim3 gp(2 * Dc / 64, (Bc * Sc) / 128);   // (32, 64)
    proj_mma_kernel<<<gp, 256, PROJ_SMEM>>>(bias);

    kmean_kernel<<<(Bc * Hc * DHc + 255) / 256, 256>>>();
    prep_k_kernel<<<((size_t)Bc * Hc * Sc * DHc / 2) / 256, 256>>>();

    dim3 ga(Sc / 128, Bc * Hc);              // (16, 64)
    attn_kernel<<<ga, 256>>>(out);
}